// round 2
// baseline (speedup 1.0000x reference)
#include <cuda_runtime.h>
#include <math.h>

// Problem dims
static constexpr int S_LEN = 512;
static constexpr int BATCH = 64;
static constexpr int IDIM  = 256;
static constexpr int HDIM  = 512;
static constexpr int EDIM  = 512;

// Persistent kernel config
static constexpr int G   = 128;   // CTAs (<=148 so all co-resident -> spin barrier is safe)
static constexpr int NT  = 256;   // threads per CTA
static constexpr int CPB = 4;     // output columns per CTA per phase (512/128)
static constexpr int PITCH = 516; // smem row pitch in floats (516%32==4 -> conflict-free float4)

static constexpr int SMEM_FLOATS = BATCH * PITCH + 3 * CPB * HDIM + 4 * 64 * CPB;
static constexpr int SMEM_BYTES  = SMEM_FLOATS * 4; // 160768 B

// Scratch state in device globals (allocation-free rule)
__device__ float g_xw[S_LEN * HDIM * BATCH];  // [t][j][b]  (x @ W_ih^T + b_ih + b_hh), 64 MB
__device__ float g_h[2][BATCH * HDIM];        // [b][k] double-buffered hidden state
__device__ float g_a[2][BATCH * EDIM];        // [b][k] double-buffered accumulator state
__device__ unsigned g_bar_count = 0;
__device__ unsigned g_bar_gen   = 0;

// ---------------------------------------------------------------------------
// Precompute: g_xw[t][j][b] = sum_i x[b][t][i] * W_ih[j][i] + b_ih[j] + b_hh[j]
// A = x viewed as (B*S, I) row-major with r = b*512 + t. Classic 64x64 tile GEMM.
// ---------------------------------------------------------------------------
__global__ __launch_bounds__(256) void xw_gemm(const float* __restrict__ x,
                                               const float* __restrict__ W_ih,
                                               const float* __restrict__ b_ih,
                                               const float* __restrict__ b_hh) {
    __shared__ float As[16][68];  // [k][r], pad 68 -> float4 LDS conflict-free
    __shared__ float Bs[16][68];  // [k][j]

    const int r0 = blockIdx.x * 64;   // over B*S = 32768
    const int j0 = blockIdx.y * 64;   // over HDIM = 512
    const int tx = threadIdx.x & 15;
    const int ty = threadIdx.x >> 4;

    float acc[4][4] = {};

    for (int k0 = 0; k0 < IDIM; k0 += 16) {
#pragma unroll
        for (int m = 0; m < 4; ++m) {
            int lin = threadIdx.x + 256 * m;      // 1024 elems per tile
            int rr = lin >> 4, kk = lin & 15;
            As[kk][rr] = x[(r0 + rr) * IDIM + k0 + kk];
            Bs[kk][rr] = W_ih[(j0 + rr) * IDIM + k0 + kk];
        }
        __syncthreads();
#pragma unroll
        for (int kk = 0; kk < 16; ++kk) {
            float4 av = *(const float4*)&As[kk][ty * 4];
            float4 bv = *(const float4*)&Bs[kk][tx * 4];
            float af[4] = {av.x, av.y, av.z, av.w};
            float bf[4] = {bv.x, bv.y, bv.z, bv.w};
#pragma unroll
            for (int i = 0; i < 4; ++i)
#pragma unroll
                for (int j = 0; j < 4; ++j)
                    acc[i][j] += af[i] * bf[j];
        }
        __syncthreads();
    }

#pragma unroll
    for (int i = 0; i < 4; ++i) {
        int r = r0 + ty * 4 + i;
        int t = r & (S_LEN - 1);
        int b = r >> 9;
#pragma unroll
        for (int j = 0; j < 4; ++j) {
            int col = j0 + tx * 4 + j;
            g_xw[(t * HDIM + col) * BATCH + b] = acc[i][j] + b_ih[col] + b_hh[col];
        }
    }
}

// ---------------------------------------------------------------------------
// Grid-wide sense barrier (generation counter; safe across graph replays)
// ---------------------------------------------------------------------------
__device__ __forceinline__ void grid_barrier() {
    __syncthreads();
    if (threadIdx.x == 0) {
        unsigned gen = *(volatile unsigned*)&g_bar_gen;  // read BEFORE arriving
        __threadfence();                                  // publish my CTA's writes
        unsigned a = atomicAdd(&g_bar_count, 1u);
        if (a == G - 1) {
            atomicExch(&g_bar_count, 0u);
            __threadfence();
            atomicAdd(&g_bar_gen, 1u);                    // release
        } else {
            while (*(volatile unsigned*)&g_bar_gen == gen) { }
        }
        __threadfence();                                  // acquire
    }
    __syncthreads();
}

// stage 64x512 state matrix from global [b][k] into smem with PITCH rows
__device__ __forceinline__ void stage_state(float* __restrict__ h_s,
                                            const float* __restrict__ src) {
    const float4* s4 = (const float4*)src;
    for (int idx = threadIdx.x; idx < BATCH * (HDIM / 4); idx += NT) {
        int bb = idx >> 7;       // HDIM/4 = 128
        int kq = idx & 127;
        *(float4*)&h_s[bb * PITCH + (kq << 2)] = s4[(bb << 7) + kq];
    }
}

// acc[c] += dot(h_s[b][ks*128 .. +128), w[c][ks*128 .. +128))
__device__ __forceinline__ void dot_panel(const float* __restrict__ h_s,
                                          const float* __restrict__ wbase,
                                          int b, int ks, float acc[CPB]) {
    const float* hr = &h_s[b * PITCH + ks * 128];
    const float* wp = &wbase[ks * 128];
#pragma unroll 8
    for (int kk = 0; kk < 128; kk += 4) {
        float4 hv = *(const float4*)&hr[kk];
#pragma unroll
        for (int c = 0; c < CPB; ++c) {
            float4 wv = *(const float4*)&wp[c * HDIM + kk];
            acc[c] += hv.x * wv.x + hv.y * wv.y + hv.z * wv.z + hv.w * wv.w;
        }
    }
}

// ---------------------------------------------------------------------------
// Persistent sequential RNN kernel
// ---------------------------------------------------------------------------
__global__ __launch_bounds__(NT, 1) void rnn_persistent(const float* __restrict__ W_hh,
                                                        const float* __restrict__ W_ya,
                                                        const float* __restrict__ W_aa,
                                                        const float* __restrict__ b_ya,
                                                        const float* __restrict__ b_aa,
                                                        float* __restrict__ out) {
    extern __shared__ float smem[];
    float* h_s = smem;                          // BATCH * PITCH (132 KB) state stage
    float* w_s = smem + BATCH * PITCH;          // 3 * CPB * 512 weight rows (24 KB)
    float* red = w_s + 3 * CPB * HDIM;          // 4 * 64 * CPB k-split reduction (4 KB)

    const int tid = threadIdx.x;
    const int bid = blockIdx.x;
    const int c0  = bid * CPB;

    // deterministic re-init every launch (graph replays)
    for (int i = bid * NT + tid; i < BATCH * HDIM; i += G * NT) g_h[0][i] = 0.f;
    for (int i = bid * NT + tid; i < BATCH * EDIM; i += G * NT) g_a[0][i] = 0.f;

    // persist this CTA's weight rows in smem for all 512 steps
    for (int idx = tid; idx < CPB * HDIM; idx += NT) {
        int c = idx >> 9, k = idx & (HDIM - 1);
        w_s[idx]                   = W_hh[(c0 + c) * HDIM + k];
        w_s[CPB * HDIM + idx]      = W_ya[(c0 + c) * HDIM + k];
        w_s[2 * CPB * HDIM + idx]  = W_aa[(c0 + c) * EDIM + k];
    }

    grid_barrier();

    const int ks = tid >> 6;   // k-split lane (4-way over K)
    const int b  = tid & 63;   // batch row
    const int cR = tid >> 6;   // reducer: column within CTA
    const int bR = tid & 63;   // reducer: batch row
    const float biasA = b_ya[c0 + cR] + b_aa[c0 + cR];

    int cur = 0;
    for (int t = 0; t < S_LEN; ++t) {
        const int nxt = cur ^ 1;

        // ---------------- phase 1: h_new = tanh(xw_t + h_old @ W_hh^T) ----------
        stage_state(h_s, g_h[cur]);
        __syncthreads();

        // prefetch xw early; it is DRAM-cold
        float xwv = g_xw[(t * HDIM + (c0 + cR)) * BATCH + bR];

        float acc[CPB] = {0.f, 0.f, 0.f, 0.f};
        dot_panel(h_s, w_s, b, ks, acc);

        *(float4*)&red[(ks * 64 + b) * 4] = make_float4(acc[0], acc[1], acc[2], acc[3]);
        __syncthreads();
        {
            float s = red[(0 * 64 + bR) * 4 + cR] + red[(1 * 64 + bR) * 4 + cR]
                    + red[(2 * 64 + bR) * 4 + cR] + red[(3 * 64 + bR) * 4 + cR];
            g_h[nxt][bR * HDIM + c0 + cR] = tanhf(s + xwv);
        }
        grid_barrier();

        // ------ phase 2: a_new = tanh(h_new @ W_ya^T + a_old @ W_aa^T + bias) ---
        stage_state(h_s, g_h[nxt]);
        __syncthreads();

        float acc2[CPB] = {0.f, 0.f, 0.f, 0.f};
        dot_panel(h_s, w_s + CPB * HDIM, b, ks, acc2);
        __syncthreads();  // done reading h_new before overwriting stage buffer

        stage_state(h_s, g_a[cur]);
        __syncthreads();
        dot_panel(h_s, w_s + 2 * CPB * HDIM, b, ks, acc2);

        *(float4*)&red[(ks * 64 + b) * 4] = make_float4(acc2[0], acc2[1], acc2[2], acc2[3]);
        __syncthreads();
        {
            float s2 = red[(0 * 64 + bR) * 4 + cR] + red[(1 * 64 + bR) * 4 + cR]
                     + red[(2 * 64 + bR) * 4 + cR] + red[(3 * 64 + bR) * 4 + cR];
            float av = tanhf(s2 + biasA);
            g_a[nxt][bR * EDIM + c0 + cR] = av;
            if (t == S_LEN - 1) out[bR * EDIM + c0 + cR] = av;
        }
        grid_barrier();

        cur = nxt;
    }
}

// ---------------------------------------------------------------------------
extern "C" void kernel_launch(void* const* d_in, const int* in_sizes, int n_in,
                              void* d_out, int out_size) {
    const float* x    = (const float*)d_in[0];
    const float* W_ih = (const float*)d_in[1];
    const float* W_hh = (const float*)d_in[2];
    const float* b_ih = (const float*)d_in[3];
    const float* b_hh = (const float*)d_in[4];
    const float* W_ya = (const float*)d_in[5];
    const float* b_ya = (const float*)d_in[6];
    const float* W_aa = (const float*)d_in[7];
    const float* b_aa = (const float*)d_in[8];
    float* out = (float*)d_out;

    cudaFuncSetAttribute(rnn_persistent,
                         cudaFuncAttributeMaxDynamicSharedMemorySize, SMEM_BYTES);

    xw_gemm<<<dim3((BATCH * S_LEN) / 64, HDIM / 64), 256>>>(x, W_ih, b_ih, b_hh);
    rnn_persistent<<<G, NT, SMEM_BYTES>>>(W_hh, W_ya, W_aa, b_ya, b_aa, out);
}

// round 3
// speedup vs baseline: 1.3344x; 1.3344x over previous
#include <cuda_runtime.h>
#include <math.h>
#include <stdint.h>

// Problem dims
static constexpr int S_LEN = 512;
static constexpr int BATCH = 64;
static constexpr int IDIM  = 256;
static constexpr int HDIM  = 512;
static constexpr int EDIM  = 512;

// Persistent kernel config: 128 CTAs = 32 col-groups x 4 k-split (one cluster each)
static constexpr int G    = 128;
static constexpr int NT   = 128;   // 4 warps
static constexpr int CPB  = 16;    // columns per CTA (cg owns 16 cols; within cluster, rank ks owns 4)
static constexpr int NKS  = 4;     // k-split factor (cluster size)

// smem layout (in ull = 8B units)
static constexpr int ST_PITCH  = 36;    // ull per state row (32 data + 4 pad)
static constexpr int W_PITCH   = 20;    // floats per weight row (16 data + 4 pad)
static constexpr int RED_PITCH = 516;   // ull per ksub slab (512 + 4 stagger)
static constexpr int OFF_ST2 = 0;                    // 256*36      = 9216 ull
static constexpr int OFF_W1  = 256 * ST_PITCH;       // 128*20 fl   = 1280 ull
static constexpr int OFF_W2  = OFF_W1 + (128 * W_PITCH) / 2;  // 256*20 fl = 2560 ull
static constexpr int OFF_RED = OFF_W2 + (256 * W_PITCH) / 2;  // 8*516     = 4128 ull
static constexpr int SMEM_ULL   = OFF_RED + 8 * RED_PITCH;
static constexpr int SMEM_BYTES = SMEM_ULL * 8;      // 137,472 B

// Device scratch (allocation-free rule)
__device__ float g_xw[S_LEN * HDIM * BATCH];     // [t][c][b]  x@W_ih^T + b_ih + b_hh
__device__ float g_h[2][HDIM * BATCH];           // [c][b] column-major state, double buffered
__device__ float g_a[2][EDIM * BATCH];
__device__ float g_part[G * CPB * BATCH];        // per-CTA partial tiles [cta][c16][b64]
__device__ unsigned g_bar_count = 0;
__device__ unsigned g_bar_gen   = 0;

// ---------------------------------------------------------------------------
// f32x2 helpers (Blackwell packed fp32 — exact 2x FFMA)
// ---------------------------------------------------------------------------
typedef unsigned long long ull;

__device__ __forceinline__ ull packdup(float w) {
    ull r; unsigned u = __float_as_uint(w);
    asm("mov.b64 %0, {%1, %2};" : "=l"(r) : "r"(u), "r"(u));
    return r;
}
__device__ __forceinline__ ull fma2(ull a, ull b, ull c) {
    ull d; asm("fma.rn.f32x2 %0, %1, %2, %3;" : "=l"(d) : "l"(a), "l"(b), "l"(c));
    return d;
}
__device__ __forceinline__ ull add2(ull a, ull b) {
    ull d; asm("add.rn.f32x2 %0, %1, %2;" : "=l"(d) : "l"(a), "l"(b));
    return d;
}

// ---------------------------------------------------------------------------
// Precompute GEMM: g_xw[t][j][b] = sum_i x[b][t][i]*W_ih[j][i] + b_ih[j] + b_hh[j]
// ---------------------------------------------------------------------------
__global__ __launch_bounds__(256) void xw_gemm(const float* __restrict__ x,
                                               const float* __restrict__ W_ih,
                                               const float* __restrict__ b_ih,
                                               const float* __restrict__ b_hh) {
    __shared__ float As[16][68];
    __shared__ float Bs[16][68];

    const int r0 = blockIdx.x * 64;
    const int j0 = blockIdx.y * 64;
    const int tx = threadIdx.x & 15;
    const int ty = threadIdx.x >> 4;

    float acc[4][4] = {};

    for (int k0 = 0; k0 < IDIM; k0 += 16) {
#pragma unroll
        for (int m = 0; m < 4; ++m) {
            int lin = threadIdx.x + 256 * m;
            int rr = lin >> 4, kk = lin & 15;
            As[kk][rr] = x[(r0 + rr) * IDIM + k0 + kk];
            Bs[kk][rr] = W_ih[(j0 + rr) * IDIM + k0 + kk];
        }
        __syncthreads();
#pragma unroll
        for (int kk = 0; kk < 16; ++kk) {
            float4 av = *(const float4*)&As[kk][ty * 4];
            float4 bv = *(const float4*)&Bs[kk][tx * 4];
            float af[4] = {av.x, av.y, av.z, av.w};
            float bf[4] = {bv.x, bv.y, bv.z, bv.w};
#pragma unroll
            for (int i = 0; i < 4; ++i)
#pragma unroll
                for (int j = 0; j < 4; ++j)
                    acc[i][j] += af[i] * bf[j];
        }
        __syncthreads();
    }

#pragma unroll
    for (int i = 0; i < 4; ++i) {
        int r = r0 + ty * 4 + i;
        int t = r & (S_LEN - 1);
        int b = r >> 9;
#pragma unroll
        for (int j = 0; j < 4; ++j) {
            int col = j0 + tx * 4 + j;
            g_xw[(t * HDIM + col) * BATCH + b] = acc[i][j] + b_ih[col] + b_hh[col];
        }
    }
}

// ---------------------------------------------------------------------------
// Grid-wide sense barrier
// ---------------------------------------------------------------------------
__device__ __forceinline__ void grid_barrier() {
    __syncthreads();
    if (threadIdx.x == 0) {
        unsigned gen = *(volatile unsigned*)&g_bar_gen;
        __threadfence();
        unsigned a = atomicAdd(&g_bar_count, 1u);
        if (a == G - 1) {
            atomicExch(&g_bar_count, 0u);
            __threadfence();
            atomicAdd(&g_bar_gen, 1u);
        } else {
            while (*(volatile unsigned*)&g_bar_gen == gen) { }
        }
        __threadfence();
    }
    __syncthreads();
}

__device__ __forceinline__ void cluster_sync_() {
    asm volatile("barrier.cluster.arrive.aligned;" ::: "memory");
    asm volatile("barrier.cluster.wait.aligned;" ::: "memory");
}

// stage `rows` state rows (64 floats each, contiguous) into st2 with pitch
__device__ __forceinline__ void stage(ull* __restrict__ st2,
                                      const float* __restrict__ src, int rows) {
    const ulonglong2* s = (const ulonglong2*)src;
    for (int i = threadIdx.x; i < rows * 16; i += NT) {
        int r = i >> 4, q = i & 15;
        ((ulonglong2*)(st2 + r * ST_PITCH))[q] = s[i];
    }
}

// register-tiled GEMM slice: acc[c 8][bp 4] += h2[k][bp] * w[k][c], k in thread range
template <int KK>
__device__ __forceinline__ void gemm_tile(const ull* __restrict__ st2,
                                          const float* __restrict__ wT,
                                          int ksub, int cg2, int bg, ull acc[8][4]) {
    const int k0 = ksub * KK;
#pragma unroll 8
    for (int kk = 0; kk < KK; ++kk) {
        const int k = k0 + kk;
        const ulonglong2* hp = (const ulonglong2*)(st2 + k * ST_PITCH + bg * 4);
        ulonglong2 h01 = hp[0];
        ulonglong2 h23 = hp[1];
        ull hv[4] = {h01.x, h01.y, h23.x, h23.y};
        const float4* wp = (const float4*)(wT + k * W_PITCH + cg2 * 8);
        float4 wa = wp[0], wb = wp[1];
        float wf[8] = {wa.x, wa.y, wa.z, wa.w, wb.x, wb.y, wb.z, wb.w};
#pragma unroll
        for (int c = 0; c < 8; ++c) {
            ull wd = packdup(wf[c]);
#pragma unroll
            for (int bp = 0; bp < 4; ++bp) acc[c][bp] = fma2(hv[bp], wd, acc[c][bp]);
        }
    }
}

// intra-CTA 8-way k-reduction through smem, then STG the 64x16 partial tile
__device__ __forceinline__ void reduce_and_emit(ull* __restrict__ red, ull acc[8][4],
                                                int ksub, int cg2, int bg,
                                                int tid, int bid) {
#pragma unroll
    for (int c = 0; c < 8; ++c) {
        ull* dst = red + ksub * RED_PITCH + (cg2 * 8 + c) * 32 + bg * 4;
        ((ulonglong2*)dst)[0] = make_ulonglong2(acc[c][0], acc[c][1]);
        ((ulonglong2*)dst)[1] = make_ulonglong2(acc[c][2], acc[c][3]);
    }
    __syncthreads();
    ull s[4] = {0ull, 0ull, 0ull, 0ull};
#pragma unroll
    for (int k2 = 0; k2 < 8; ++k2) {
        const ulonglong2* src = (const ulonglong2*)(red + k2 * RED_PITCH + tid * 4);
        ulonglong2 a = src[0], b = src[1];
        s[0] = add2(s[0], a.x); s[1] = add2(s[1], a.y);
        s[2] = add2(s[2], b.x); s[3] = add2(s[3], b.y);
    }
    float* gp = g_part + bid * (CPB * BATCH) + (tid >> 3) * BATCH + (tid & 7) * 8;
    ((ulonglong2*)gp)[0] = make_ulonglong2(s[0], s[1]);
    ((ulonglong2*)gp)[1] = make_ulonglong2(s[2], s[3]);
}

// ---------------------------------------------------------------------------
// Persistent RNN kernel: G=128 CTAs, clusters of 4 (the k-splits of one cg)
// ---------------------------------------------------------------------------
__global__ __launch_bounds__(NT, 1) __cluster_dims__(NKS, 1, 1)
void rnn_persistent(const float* __restrict__ W_hh,
                    const float* __restrict__ W_ya,
                    const float* __restrict__ W_aa,
                    const float* __restrict__ b_ya,
                    const float* __restrict__ b_aa,
                    float* __restrict__ out) {
    extern __shared__ ull smem_u[];
    ull*   st2 = smem_u + OFF_ST2;
    float* wT1 = (float*)(smem_u + OFF_W1);
    float* wT2 = (float*)(smem_u + OFF_W2);
    ull*   red = smem_u + OFF_RED;

    const int tid = threadIdx.x;
    const int bid = blockIdx.x;
    const int cg  = bid >> 2;       // column group 0..31
    const int ks  = bid & 3;        // k-split rank (== cluster rank)

    // thread roles for the GEMM tile
    const int ksub = tid >> 4;          // 0..7  (intra-CTA k split)
    const int cg2  = (tid >> 3) & 1;    // 0..1  (8-col halves)
    const int bg   = tid & 7;           // 0..7  (4 batch-pairs each)

    // zero-init state buffers (deterministic per replay)
    for (int i = bid * NT + tid; i < HDIM * BATCH; i += G * NT) g_h[0][i] = 0.f;
    for (int i = bid * NT + tid; i < EDIM * BATCH; i += G * NT) g_a[0][i] = 0.f;

    // resident weight slices (transposed, padded)
    for (int i = tid; i < CPB * 128; i += NT) {
        int c = i >> 7, k = i & 127;
        wT1[k * W_PITCH + c] = W_hh[(cg * CPB + c) * HDIM + ks * 128 + k];
    }
    for (int i = tid; i < CPB * 256; i += NT) {
        int c = i >> 8, k = i & 255;
        int kg = (ks & 1) * 256 + k;
        wT2[k * W_PITCH + c] = (ks < 2) ? W_ya[(cg * CPB + c) * HDIM + kg]
                                        : W_aa[(cg * CPB + c) * EDIM + kg];
    }

    // owner-final role: this CTA finalizes global cols cg*16 + ks*4 .. +4
    const int ciA = tid >> 6;               // 0..1 ; second rep adds +2
    const int bF  = tid & 63;
    const int cA  = cg * CPB + ks * 4 + ciA;
    const int cB  = cA + 2;
    const float biasA = b_ya[cA] + b_aa[cA];
    const float biasB = b_ya[cB] + b_aa[cB];

    grid_barrier();

    int cur = 0;
    for (int t = 0; t < S_LEN; ++t) {
        const int nxt = cur ^ 1;

        // ===== phase 1: h_new = tanh(xw_t + h_old @ W_hh^T), k-split over cluster =====
        stage(st2, g_h[cur] + ks * 128 * BATCH, 128);
        __syncthreads();
        {
            ull acc[8][4] = {};
            gemm_tile<16>(st2, wT1, ksub, cg2, bg, acc);
            reduce_and_emit(red, acc, ksub, cg2, bg, tid, bid);
        }
        cluster_sync_();   // partials of the 4 k-splits now visible cluster-wide
        {
            const int base = (bid & ~3) * (CPB * BATCH);
            float vA = 0.f, vB = 0.f;
#pragma unroll
            for (int p = 0; p < NKS; ++p) {
                const float* pp = g_part + base + p * (CPB * BATCH);
                vA += pp[(ks * 4 + ciA) * BATCH + bF];
                vB += pp[(ks * 4 + ciA + 2) * BATCH + bF];
            }
            vA += g_xw[(t * HDIM + cA) * BATCH + bF];
            vB += g_xw[(t * HDIM + cB) * BATCH + bF];
            g_h[nxt][cA * BATCH + bF] = tanhf(vA);
            g_h[nxt][cB * BATCH + bF] = tanhf(vB);
        }
        grid_barrier();

        // ===== phase 2: a_new = tanh(h_new@W_ya^T + a_old@W_aa^T + bias), K=1024 split =====
        {
            const float* src2 = (ks < 2) ? (g_h[nxt] + ks * 256 * BATCH)
                                         : (g_a[cur] + (ks & 1) * 256 * BATCH);
            stage(st2, src2, 256);
        }
        __syncthreads();
        {
            ull acc[8][4] = {};
            gemm_tile<32>(st2, wT2, ksub, cg2, bg, acc);
            reduce_and_emit(red, acc, ksub, cg2, bg, tid, bid);
        }
        cluster_sync_();
        {
            const int base = (bid & ~3) * (CPB * BATCH);
            float vA = 0.f, vB = 0.f;
#pragma unroll
            for (int p = 0; p < NKS; ++p) {
                const float* pp = g_part + base + p * (CPB * BATCH);
                vA += pp[(ks * 4 + ciA) * BATCH + bF];
                vB += pp[(ks * 4 + ciA + 2) * BATCH + bF];
            }
            float aA = tanhf(vA + biasA);
            float aB = tanhf(vB + biasB);
            g_a[nxt][cA * BATCH + bF] = aA;
            g_a[nxt][cB * BATCH + bF] = aB;
            if (t == S_LEN - 1) {
                out[bF * EDIM + cA] = aA;
                out[bF * EDIM + cB] = aB;
            }
        }
        grid_barrier();

        cur = nxt;
    }
}

// ---------------------------------------------------------------------------
extern "C" void kernel_launch(void* const* d_in, const int* in_sizes, int n_in,
                              void* d_out, int out_size) {
    const float* x    = (const float*)d_in[0];
    const float* W_ih = (const float*)d_in[1];
    const float* W_hh = (const float*)d_in[2];
    const float* b_ih = (const float*)d_in[3];
    const float* b_hh = (const float*)d_in[4];
    const float* W_ya = (const float*)d_in[5];
    const float* b_ya = (const float*)d_in[6];
    const float* W_aa = (const float*)d_in[7];
    const float* b_aa = (const float*)d_in[8];
    float* out = (float*)d_out;

    cudaFuncSetAttribute(rnn_persistent,
                         cudaFuncAttributeMaxDynamicSharedMemorySize, SMEM_BYTES);

    xw_gemm<<<dim3((BATCH * S_LEN) / 64, HDIM / 64), 256>>>(x, W_ih, b_ih, b_hh);
    rnn_persistent<<<G, NT, SMEM_BYTES>>>(W_hh, W_ya, W_aa, b_ya, b_aa, out);
}